// round 1
// baseline (speedup 1.0000x reference)
#include <cuda_runtime.h>
#include <cstdint>

typedef unsigned long long u64;

__device__ float g_u_tgt;

// Compute u(target) = MLP(6.2562059, 6.2562059) once per launch.
__global__ void utgt_kernel(const float* __restrict__ W1, const float* __restrict__ b1,
                            const float* __restrict__ W2, const float* __restrict__ b2,
                            const float* __restrict__ W3, const float* __restrict__ b3) {
    __shared__ float h1[64];
    __shared__ float part[64];
    int t = threadIdx.x;  // 64 threads
    const float tt = 6.2562059f;
    float h = fmaf(W1[2 * t], tt, fmaf(W1[2 * t + 1], tt, b1[t]));
    h1[t] = fmaxf(h, 0.f);
    __syncthreads();
    float acc = b2[t];
#pragma unroll
    for (int k = 0; k < 64; k++) acc = fmaf(W2[t * 64 + k], h1[k], acc);
    part[t] = W3[t] * fmaxf(acc, 0.f);
    __syncthreads();
    if (t == 0) {
        float s = b3[0];
#pragma unroll
        for (int k = 0; k < 64; k++) s += part[k];
        g_u_tgt = s;
    }
}

__device__ __forceinline__ void hill_out(float* __restrict__ out, int n, int i,
                                         float xv, float yv, float u) {
    float xs = xv * 0.1f, ys = yv * 0.1f;
    float x2 = xs * xs, y2 = ys * ys;
    float ivx = 1.f / (0.25f + x2);
    float ivy = 1.f / (0.25f + y2);
    float hx = x2 * ivx, hy = y2 * ivy;
    float gx = 0.25f * ivx, gy = 0.25f * ivy;
    float dx = 10.f * (hx + 0.2f * gy - 1.1f * xs + u * hx);
    float dy = 10.f * (hy + 0.2f * gx - 1.1f * ys);
    out[i] = dx;
    out[n + i] = dy;
    out[2 * n + i] = -dx;
    out[3 * n + i] = -dy;
}

__global__ void __launch_bounds__(128) netc_kernel(
    const float* __restrict__ x, const float* __restrict__ y,
    const float* __restrict__ ex, const float* __restrict__ ey,
    const float* __restrict__ W1, const float* __restrict__ b1,
    const float* __restrict__ W2, const float* __restrict__ b2,
    const float* __restrict__ W3, const float* __restrict__ b3,
    float* __restrict__ out, int n, int half) {
    __shared__ u64 w2d[64 * 64];   // W2 duplicated (w,w) pairs: 32 KB
    __shared__ u64 b2d[64];
    __shared__ float w1s[128];
    __shared__ float b1s[64];
    __shared__ float w3s[64];

    int tid = threadIdx.x;
    for (int i = tid; i < 4096; i += 128) {
        unsigned w = __float_as_uint(W2[i]);
        w2d[i] = ((u64)w << 32) | (u64)w;
    }
    if (tid < 64) {
        unsigned v = __float_as_uint(b2[tid]);
        b2d[tid] = ((u64)v << 32) | (u64)v;
        b1s[tid] = b1[tid];
        w3s[tid] = W3[tid];
    }
    w1s[tid] = W1[tid];  // W1 has 64*2 = 128 elements, blockDim == 128
    __syncthreads();

    int i0 = blockIdx.x * 128 + tid;
    if (i0 >= half) return;
    int i1 = i0 + half;
    bool has1 = (i1 < n);
    int i1c = has1 ? i1 : i0;

    float x0 = x[i0], y0 = y[i0];
    float a0 = x0 + ex[i0], c0 = y0 + ey[i0];
    float x1 = x[i1c], y1 = y[i1c];
    float a1 = x1 + ex[i1c], c1 = y1 + ey[i1c];

    // Layer 1: h1 packed as (elem0 in lo, elem1 in hi), kept in registers.
    u64 h1p[64];
#pragma unroll
    for (int k = 0; k < 64; k++) {
        float wA = w1s[2 * k], wB = w1s[2 * k + 1], bb = b1s[k];
        float h0 = fmaxf(fmaf(wA, a0, fmaf(wB, c0, bb)), 0.f);
        float h1 = fmaxf(fmaf(wA, a1, fmaf(wB, c1, bb)), 0.f);
        h1p[k] = ((u64)__float_as_uint(h1) << 32) | (u64)__float_as_uint(h0);
    }

    // Layer 2 + 3: per output neuron j, packed dot over k with 4 accumulators.
    float o0 = 0.f, o1 = 0.f;
#pragma unroll 1
    for (int j = 0; j < 64; j++) {
        const u64* wr = &w2d[j << 6];
        u64 a0q = b2d[j], a1q = 0ull, a2q = 0ull, a3q = 0ull;
#pragma unroll
        for (int k = 0; k < 64; k += 4) {
            asm("fma.rn.f32x2 %0, %1, %2, %0;" : "+l"(a0q) : "l"(wr[k + 0]), "l"(h1p[k + 0]));
            asm("fma.rn.f32x2 %0, %1, %2, %0;" : "+l"(a1q) : "l"(wr[k + 1]), "l"(h1p[k + 1]));
            asm("fma.rn.f32x2 %0, %1, %2, %0;" : "+l"(a2q) : "l"(wr[k + 2]), "l"(h1p[k + 2]));
            asm("fma.rn.f32x2 %0, %1, %2, %0;" : "+l"(a3q) : "l"(wr[k + 3]), "l"(h1p[k + 3]));
        }
        asm("add.rn.f32x2 %0, %0, %1;" : "+l"(a0q) : "l"(a1q));
        asm("add.rn.f32x2 %0, %0, %1;" : "+l"(a2q) : "l"(a3q));
        asm("add.rn.f32x2 %0, %0, %1;" : "+l"(a0q) : "l"(a2q));
        float h0 = __uint_as_float((unsigned)(a0q & 0xffffffffu));
        float h1v = __uint_as_float((unsigned)(a0q >> 32));
        float w3 = w3s[j];
        o0 = fmaf(w3, fmaxf(h0, 0.f), o0);
        o1 = fmaf(w3, fmaxf(h1v, 0.f), o1);
    }

    float bias3 = b3[0];
    float ut = g_u_tgt;
    float u0 = o0 + bias3 - ut;
    float u1 = o1 + bias3 - ut;

    hill_out(out, n, i0, x0, y0, u0);
    if (has1) hill_out(out, n, i1, x1, y1, u1);
}

extern "C" void kernel_launch(void* const* d_in, const int* in_sizes, int n_in,
                              void* d_out, int out_size) {
    const float* x  = (const float*)d_in[0];
    const float* y  = (const float*)d_in[1];
    const float* ex = (const float*)d_in[2];
    const float* ey = (const float*)d_in[3];
    const float* W1 = (const float*)d_in[4];
    const float* b1 = (const float*)d_in[5];
    const float* W2 = (const float*)d_in[6];
    const float* b2 = (const float*)d_in[7];
    const float* W3 = (const float*)d_in[8];
    const float* b3 = (const float*)d_in[9];
    int n = in_sizes[0];
    int half = (n + 1) / 2;

    utgt_kernel<<<1, 64>>>(W1, b1, W2, b2, W3, b3);
    int blocks = (half + 127) / 128;
    netc_kernel<<<blocks, 128>>>(x, y, ex, ey, W1, b1, W2, b2, W3, b3,
                                 (float*)d_out, n, half);
}